// round 5
// baseline (speedup 1.0000x reference)
#include <cuda_runtime.h>
#include <stdint.h>

// SpikeFP8Adder_Spatial: soft-logic E4M3 adder on {0,1}-valued float bit vectors.
// Exact 0/1 inputs => gate network collapses to integer bit logic.
// Pure HBM-bound (384 MB). R5: persistent single-wave grid (SMs x 8 CTAs),
// grid-stride loop, 2 rows/iteration with 8 front-batched streaming loads.

__device__ __forceinline__ void fp8add_row(
    const uint4& a0, const uint4& a1,
    const uint4& b0, const uint4& b1,
    uint4& o0, uint4& o1)
{
    // Pack MSB-first: index 0 -> bit7 ... index 7 -> bit0. 1.0f = 0x3F800000 (bit 23 set).
    unsigned pa =
        (((a0.x >> 23) & 1u) << 7) | (((a0.y >> 23) & 1u) << 6) |
        (((a0.z >> 23) & 1u) << 5) | (((a0.w >> 23) & 1u) << 4) |
        (((a1.x >> 23) & 1u) << 3) | (((a1.y >> 23) & 1u) << 2) |
        (((a1.z >> 23) & 1u) << 1) |  ((a1.w >> 23) & 1u);
    unsigned pb =
        (((b0.x >> 23) & 1u) << 7) | (((b0.y >> 23) & 1u) << 6) |
        (((b0.z >> 23) & 1u) << 5) | (((b0.w >> 23) & 1u) << 4) |
        (((b1.x >> 23) & 1u) << 3) | (((b1.y >> 23) & 1u) << 2) |
        (((b1.z >> 23) & 1u) << 1) |  ((b1.w >> 23) & 1u);

    unsigned sa = (pa >> 7) & 1u, ea = (pa >> 3) & 15u, ma = pa & 7u;
    unsigned sb = (pb >> 7) & 1u, eb = (pb >> 3) & 15u, mb = pb & 7u;

    bool sel = (ea >= eb);
    unsigned el = sel ? ea : eb;
    unsigned es = sel ? eb : ea;
    unsigned ml = sel ? ma : mb;
    unsigned ms = sel ? mb : ma;
    unsigned sl = sel ? sa : sb;
    unsigned ss = sel ? sb : sa;

    unsigned diff = el - es;

    unsigned extl = ((el != 0u) ? 0x400u : 0u) | (ml << 7);
    unsigned exts = (((es != 0u) ? 0x400u : 0u) | (ms << 7)) >> diff;

    unsigned mant = (sl == ss) ? ((extl + exts) & 0xFFFu)
                               : ((extl - exts) & 0xFFFu);

    unsigned top8 = mant >> 4;
    unsigned lzc = top8 ? (unsigned)(__clz((int)top8) - 24) : 7u;
    unsigned norm = (top8 << lzc) & 0xFFu;
    unsigned en = (el - lzc + 1u) & 15u;

    const unsigned ONE = 0x3F800000u;
    o0.x = sl * ONE;
    o0.y = ((en >> 3) & 1u) * ONE;
    o0.z = ((en >> 2) & 1u) * ONE;
    o0.w = ((en >> 1) & 1u) * ONE;
    o1.x = (en & 1u) * ONE;
    o1.y = ((norm >> 6) & 1u) * ONE;
    o1.z = ((norm >> 5) & 1u) * ONE;
    o1.w = ((norm >> 4) & 1u) * ONE;
}

__global__ __launch_bounds__(256, 8) void fp8add_persistent(
    const uint4* __restrict__ A,
    const uint4* __restrict__ B,
    uint4* __restrict__ O,
    int half)   // nrows / 2
{
    int stride = gridDim.x * blockDim.x;
    for (int i = blockIdx.x * blockDim.x + threadIdx.x; i < half; i += stride) {
        int j = i + half;

        // Front-batch all 8 loads (streaming, evict-first) for maximum MLP.
        uint4 a0 = __ldcs(&A[2 * i + 0]);
        uint4 a1 = __ldcs(&A[2 * i + 1]);
        uint4 b0 = __ldcs(&B[2 * i + 0]);
        uint4 b1 = __ldcs(&B[2 * i + 1]);
        uint4 c0 = __ldcs(&A[2 * j + 0]);
        uint4 c1 = __ldcs(&A[2 * j + 1]);
        uint4 d0 = __ldcs(&B[2 * j + 0]);
        uint4 d1 = __ldcs(&B[2 * j + 1]);

        uint4 o0, o1;
        fp8add_row(a0, a1, b0, b1, o0, o1);
        __stcs(&O[2 * i + 0], o0);
        __stcs(&O[2 * i + 1], o1);

        fp8add_row(c0, c1, d0, d1, o0, o1);
        __stcs(&O[2 * j + 0], o0);
        __stcs(&O[2 * j + 1], o1);
    }
}

__global__ __launch_bounds__(256) void fp8add_tail(
    const uint4* __restrict__ A,
    const uint4* __restrict__ B,
    uint4* __restrict__ O,
    int nrows, int start)
{
    int i = start + blockIdx.x * blockDim.x + threadIdx.x;
    if (i >= nrows) return;
    uint4 a0 = __ldcs(&A[2 * i + 0]);
    uint4 a1 = __ldcs(&A[2 * i + 1]);
    uint4 b0 = __ldcs(&B[2 * i + 0]);
    uint4 b1 = __ldcs(&B[2 * i + 1]);
    uint4 o0, o1;
    fp8add_row(a0, a1, b0, b1, o0, o1);
    __stcs(&O[2 * i + 0], o0);
    __stcs(&O[2 * i + 1], o1);
}

extern "C" void kernel_launch(void* const* d_in, const int* in_sizes, int n_in,
                              void* d_out, int out_size)
{
    const uint4* A = (const uint4*)d_in[0];
    const uint4* B = (const uint4*)d_in[1];
    uint4* O = (uint4*)d_out;

    int nrows = in_sizes[0] / 8;
    int half = nrows >> 1;
    int threads = 256;

    // Single-wave persistent grid: SM count x 8 CTAs/SM (regs capped at 32).
    int sms = 148;
    cudaDeviceGetAttribute(&sms, cudaDevAttrMultiProcessorCount, 0);
    int blocks = sms * 8;
    int max_blocks = (half + threads - 1) / threads;
    if (blocks > max_blocks) blocks = max_blocks;

    if (half > 0) {
        fp8add_persistent<<<blocks, threads>>>(A, B, O, half);
    }
    if (nrows & 1) {
        // odd tail row (not hit for N=4194304, kept for generality)
        fp8add_tail<<<1, threads>>>(A, B, O, nrows, nrows - 1);
    }
}

// round 6
// speedup vs baseline: 1.1106x; 1.1106x over previous
#include <cuda_runtime.h>
#include <stdint.h>

// SpikeFP8Adder_Spatial: soft-logic E4M3 adder on {0,1}-valued float bit vectors.
// Exact 0/1 inputs => gate network collapses to integer bit logic.
// Pure HBM-bound (384 MB). R6: fire-and-exit CTAs (best from R2/R5 sweep),
// 2 ADJACENT rows/thread -> 64B contiguous per thread, 3 address streams total,
// 8 front-batched streaming loads per thread.

__device__ __forceinline__ void fp8add_row(
    const uint4& a0, const uint4& a1,
    const uint4& b0, const uint4& b1,
    uint4& o0, uint4& o1)
{
    // Pack MSB-first: index 0 -> bit7 ... index 7 -> bit0. 1.0f = 0x3F800000 (bit 23 set).
    unsigned pa =
        (((a0.x >> 23) & 1u) << 7) | (((a0.y >> 23) & 1u) << 6) |
        (((a0.z >> 23) & 1u) << 5) | (((a0.w >> 23) & 1u) << 4) |
        (((a1.x >> 23) & 1u) << 3) | (((a1.y >> 23) & 1u) << 2) |
        (((a1.z >> 23) & 1u) << 1) |  ((a1.w >> 23) & 1u);
    unsigned pb =
        (((b0.x >> 23) & 1u) << 7) | (((b0.y >> 23) & 1u) << 6) |
        (((b0.z >> 23) & 1u) << 5) | (((b0.w >> 23) & 1u) << 4) |
        (((b1.x >> 23) & 1u) << 3) | (((b1.y >> 23) & 1u) << 2) |
        (((b1.z >> 23) & 1u) << 1) |  ((b1.w >> 23) & 1u);

    unsigned sa = (pa >> 7) & 1u, ea = (pa >> 3) & 15u, ma = pa & 7u;
    unsigned sb = (pb >> 7) & 1u, eb = (pb >> 3) & 15u, mb = pb & 7u;

    bool sel = (ea >= eb);
    unsigned el = sel ? ea : eb;
    unsigned es = sel ? eb : ea;
    unsigned ml = sel ? ma : mb;
    unsigned ms = sel ? mb : ma;
    unsigned sl = sel ? sa : sb;
    unsigned ss = sel ? sb : sa;

    unsigned diff = el - es;

    unsigned extl = ((el != 0u) ? 0x400u : 0u) | (ml << 7);
    unsigned exts = (((es != 0u) ? 0x400u : 0u) | (ms << 7)) >> diff;

    unsigned mant = (sl == ss) ? ((extl + exts) & 0xFFFu)
                               : ((extl - exts) & 0xFFFu);

    unsigned top8 = mant >> 4;
    unsigned lzc = top8 ? (unsigned)(__clz((int)top8) - 24) : 7u;
    unsigned norm = (top8 << lzc) & 0xFFu;
    unsigned en = (el - lzc + 1u) & 15u;

    const unsigned ONE = 0x3F800000u;
    o0.x = sl * ONE;
    o0.y = ((en >> 3) & 1u) * ONE;
    o0.z = ((en >> 2) & 1u) * ONE;
    o0.w = ((en >> 1) & 1u) * ONE;
    o1.x = (en & 1u) * ONE;
    o1.y = ((norm >> 6) & 1u) * ONE;
    o1.z = ((norm >> 5) & 1u) * ONE;
    o1.w = ((norm >> 4) & 1u) * ONE;
}

__global__ __launch_bounds__(256) void fp8add_adj2(
    const uint4* __restrict__ A,
    const uint4* __restrict__ B,
    uint4* __restrict__ O,
    int half)   // nrows / 2 (thread t handles rows 2t, 2t+1)
{
    int t = blockIdx.x * blockDim.x + threadIdx.x;
    if (t >= half) return;
    int base = 4 * t;   // uint4 index; 64B contiguous per operand per thread

    // Front-batch all 8 loads (streaming, evict-first) for maximum MLP.
    uint4 a0 = __ldcs(&A[base + 0]);
    uint4 a1 = __ldcs(&A[base + 1]);
    uint4 a2 = __ldcs(&A[base + 2]);
    uint4 a3 = __ldcs(&A[base + 3]);
    uint4 b0 = __ldcs(&B[base + 0]);
    uint4 b1 = __ldcs(&B[base + 1]);
    uint4 b2 = __ldcs(&B[base + 2]);
    uint4 b3 = __ldcs(&B[base + 3]);

    uint4 o0, o1, o2, o3;
    fp8add_row(a0, a1, b0, b1, o0, o1);
    fp8add_row(a2, a3, b2, b3, o2, o3);

    __stcs(&O[base + 0], o0);
    __stcs(&O[base + 1], o1);
    __stcs(&O[base + 2], o2);
    __stcs(&O[base + 3], o3);
}

__global__ __launch_bounds__(256) void fp8add_tail(
    const uint4* __restrict__ A,
    const uint4* __restrict__ B,
    uint4* __restrict__ O,
    int nrows, int start)
{
    int i = start + blockIdx.x * blockDim.x + threadIdx.x;
    if (i >= nrows) return;
    uint4 a0 = __ldcs(&A[2 * i + 0]);
    uint4 a1 = __ldcs(&A[2 * i + 1]);
    uint4 b0 = __ldcs(&B[2 * i + 0]);
    uint4 b1 = __ldcs(&B[2 * i + 1]);
    uint4 o0, o1;
    fp8add_row(a0, a1, b0, b1, o0, o1);
    __stcs(&O[2 * i + 0], o0);
    __stcs(&O[2 * i + 1], o1);
}

extern "C" void kernel_launch(void* const* d_in, const int* in_sizes, int n_in,
                              void* d_out, int out_size)
{
    const uint4* A = (const uint4*)d_in[0];
    const uint4* B = (const uint4*)d_in[1];
    uint4* O = (uint4*)d_out;

    int nrows = in_sizes[0] / 8;
    int half = nrows >> 1;
    int threads = 256;

    if (half > 0) {
        int blocks = (half + threads - 1) / threads;
        fp8add_adj2<<<blocks, threads>>>(A, B, O, half);
    }
    if (nrows & 1) {
        // odd tail row (not hit for N=4194304, kept for generality)
        fp8add_tail<<<1, threads>>>(A, B, O, nrows, nrows - 1);
    }
}

// round 7
// speedup vs baseline: 1.1265x; 1.0143x over previous
#include <cuda_runtime.h>
#include <stdint.h>

// SpikeFP8Adder_Spatial: soft-logic E4M3 adder on {0,1}-valued float bit vectors.
// Exact 0/1 inputs => gate network collapses to integer bit logic.
// Pure HBM-bound (384 MB). R7: warp-tiled 64 rows, perfectly-coalesced 16B-lane-stride
// LDG/STG.128 (4 lines/instr instead of 8), half-row exchange via 2 butterfly shuffles.

__device__ __forceinline__ unsigned fp8add_byte(unsigned pa, unsigned pb)
{
    unsigned sa = (pa >> 7) & 1u, ea = (pa >> 3) & 15u, ma = pa & 7u;
    unsigned sb = (pb >> 7) & 1u, eb = (pb >> 3) & 15u, mb = pb & 7u;

    bool sel = (ea >= eb);
    unsigned el = sel ? ea : eb;
    unsigned es = sel ? eb : ea;
    unsigned ml = sel ? ma : mb;
    unsigned ms = sel ? mb : ma;
    unsigned sl = sel ? sa : sb;
    unsigned ss = sel ? sb : sa;

    unsigned diff = el - es;

    unsigned extl = ((el != 0u) ? 0x400u : 0u) | (ml << 7);
    unsigned exts = (((es != 0u) ? 0x400u : 0u) | (ms << 7)) >> diff;

    unsigned mant = (sl == ss) ? ((extl + exts) & 0xFFFu)
                               : ((extl - exts) & 0xFFFu);

    unsigned top8 = mant >> 4;
    unsigned lzc = top8 ? (unsigned)(__clz((int)top8) - 24) : 7u;
    unsigned norm = (top8 << lzc) & 0xFFu;
    unsigned en = (el - lzc + 1u) & 15u;

    // Output byte MSB-first: sign | exp(4) | norm bits 6..4
    return (sl << 7) | (en << 3) | ((norm >> 4) & 7u);
}

// nibble MSB-first from a 16B float vector: x->bit3 ... w->bit0 (1.0f has bit 23 set)
__device__ __forceinline__ unsigned nib4(const uint4& v)
{
    return (((v.x >> 23) & 1u) << 3) | (((v.y >> 23) & 1u) << 2) |
           (((v.z >> 23) & 1u) << 1) |  ((v.w >> 23) & 1u);
}

// Warp tile: 64 consecutive rows = 128 consecutive uint4 per tensor.
// Lane l loads uint4 indices Wbase + 32k + l (16B lane stride, k=0..3) from A and B.
// uint4 (Wbase + 32k + l) = half (l&1) of row (R0 + 16k + (l>>1)).
// Lanes 2t / 2t+1 hold hi / lo halves of the same 4 rows -> one xor-1 shuffle pairs them.
// Even lane computes rows k=0,1; odd lane rows k=2,3 (rows R0 + 16k + t).
__global__ __launch_bounds__(256) void fp8add_warp64(
    const uint4* __restrict__ A,
    const uint4* __restrict__ B,
    uint4* __restrict__ O,
    int nwarps)
{
    int gtid = blockIdx.x * blockDim.x + threadIdx.x;
    int warp = gtid >> 5;
    if (warp >= nwarps) return;
    int l = gtid & 31;
    int odd = l & 1;
    int Wbase = warp * 128;

    // 8 front-batched loads, 16B lane stride (perfect coalescing), streaming.
    uint4 a0 = __ldcs(&A[Wbase +       l]);
    uint4 a1 = __ldcs(&A[Wbase +  32 + l]);
    uint4 a2 = __ldcs(&A[Wbase +  64 + l]);
    uint4 a3 = __ldcs(&A[Wbase +  96 + l]);
    uint4 b0 = __ldcs(&B[Wbase +       l]);
    uint4 b1 = __ldcs(&B[Wbase +  32 + l]);
    uint4 b2 = __ldcs(&B[Wbase +  64 + l]);
    uint4 b3 = __ldcs(&B[Wbase +  96 + l]);

    // Reduce each 16B vector to a 4-bit nibble; pack all 8 into one word.
    unsigned own = nib4(a0) | (nib4(a1) << 4) | (nib4(a2) << 8)  | (nib4(a3) << 12)
                 | (nib4(b0) << 16) | (nib4(b1) << 20) | (nib4(b2) << 24) | (nib4(b3) << 28);
    unsigned part = __shfl_xor_sync(0xffffffffu, own, 1);

    unsigned hi = odd ? part : own;   // hi-half nibbles (A slots 0..3, B slots 4..7)
    unsigned lo = odd ? own : part;   // lo-half nibbles

    // This thread's two rows use nibble slots k0, k0+1.
    unsigned k0 = (unsigned)(odd << 1);
    unsigned s0 = 4u * k0;            // A slot shift for k0
    unsigned pa0 = (((hi >> s0) & 15u) << 4)        | ((lo >> s0) & 15u);
    unsigned pb0 = (((hi >> (16u + s0)) & 15u) << 4) | ((lo >> (16u + s0)) & 15u);
    unsigned pa1 = (((hi >> (s0 + 4u)) & 15u) << 4)  | ((lo >> (s0 + 4u)) & 15u);
    unsigned pb1 = (((hi >> (20u + s0)) & 15u) << 4) | ((lo >> (20u + s0)) & 15u);

    unsigned ob0 = fp8add_byte(pa0, pb0);
    unsigned ob1 = fp8add_byte(pa1, pb1);

    // Exchange output bytes with partner lane; then store 4 uint4 at 16B lane stride.
    unsigned po  = ob0 | (ob1 << 8);
    unsigned ppo = __shfl_xor_sync(0xffffffffu, po, 1);

    const unsigned ONE = 0x3F800000u;
#pragma unroll
    for (int k = 0; k < 4; k++) {
        bool ownrow = ((k < 2) == (odd == 0));
        unsigned byte = ownrow ? ((k & 1) ? ob1 : ob0)
                               : ((ppo >> (8 * (k & 1))) & 255u);
        unsigned nb = odd ? (byte & 15u) : (byte >> 4);
        uint4 o;
        o.x = ((nb >> 3) & 1u) * ONE;
        o.y = ((nb >> 2) & 1u) * ONE;
        o.z = ((nb >> 1) & 1u) * ONE;
        o.w = ( nb        & 1u) * ONE;
        __stcs(&O[Wbase + 32 * k + l], o);
    }
}

// 1 row/thread tail for nrows not divisible by 64 (not hit for N=4194304).
__global__ __launch_bounds__(256) void fp8add_tail(
    const uint4* __restrict__ A,
    const uint4* __restrict__ B,
    uint4* __restrict__ O,
    int nrows, int start)
{
    int i = start + blockIdx.x * blockDim.x + threadIdx.x;
    if (i >= nrows) return;
    uint4 a0 = __ldcs(&A[2 * i + 0]);
    uint4 a1 = __ldcs(&A[2 * i + 1]);
    uint4 b0 = __ldcs(&B[2 * i + 0]);
    uint4 b1 = __ldcs(&B[2 * i + 1]);
    unsigned pa = (nib4(a0) << 4) | nib4(a1);
    unsigned pb = (nib4(b0) << 4) | nib4(b1);
    unsigned ob = fp8add_byte(pa, pb);
    const unsigned ONE = 0x3F800000u;
    uint4 o0, o1;
    o0.x = ((ob >> 7) & 1u) * ONE;
    o0.y = ((ob >> 6) & 1u) * ONE;
    o0.z = ((ob >> 5) & 1u) * ONE;
    o0.w = ((ob >> 4) & 1u) * ONE;
    o1.x = ((ob >> 3) & 1u) * ONE;
    o1.y = ((ob >> 2) & 1u) * ONE;
    o1.z = ((ob >> 1) & 1u) * ONE;
    o1.w = ( ob        & 1u) * ONE;
    __stcs(&O[2 * i + 0], o0);
    __stcs(&O[2 * i + 1], o1);
}

extern "C" void kernel_launch(void* const* d_in, const int* in_sizes, int n_in,
                              void* d_out, int out_size)
{
    const uint4* A = (const uint4*)d_in[0];
    const uint4* B = (const uint4*)d_in[1];
    uint4* O = (uint4*)d_out;

    int nrows = in_sizes[0] / 8;
    int nwarps = nrows / 64;          // full 64-row warp tiles
    int threads = 256;                // 8 warps per block

    if (nwarps > 0) {
        int blocks = (nwarps + 7) / 8;
        fp8add_warp64<<<blocks, threads>>>(A, B, O, nwarps);
    }
    int done = nwarps * 64;
    int rem = nrows - done;
    if (rem > 0) {
        int blocks = (rem + threads - 1) / threads;
        fp8add_tail<<<blocks, threads>>>(A, B, O, nrows, done);
    }
}

// round 8
// speedup vs baseline: 1.1312x; 1.0041x over previous
#include <cuda_runtime.h>
#include <stdint.h>

// SpikeFP8Adder_Spatial: soft-logic E4M3 adder on {0,1}-valued float bit vectors.
// Exact 0/1 inputs => gate network collapses to integer bit logic.
// Pure HBM-bound (384 MB, 2:1 read:write => ~81% of spec is the practical ceiling).
// R8: best-known config (R2: 2 strided rows/thread, 8 front-batched streaming
// loads, fire-and-exit CTAs) with 128-thread blocks for finer CTA quantization
// (6x256=1536 -> 13x128=1664 resident threads/SM at 38 regs).

__device__ __forceinline__ void fp8add_row(
    const uint4& a0, const uint4& a1,
    const uint4& b0, const uint4& b1,
    uint4& o0, uint4& o1)
{
    // Pack MSB-first: index 0 -> bit7 ... index 7 -> bit0. 1.0f = 0x3F800000 (bit 23 set).
    unsigned pa =
        (((a0.x >> 23) & 1u) << 7) | (((a0.y >> 23) & 1u) << 6) |
        (((a0.z >> 23) & 1u) << 5) | (((a0.w >> 23) & 1u) << 4) |
        (((a1.x >> 23) & 1u) << 3) | (((a1.y >> 23) & 1u) << 2) |
        (((a1.z >> 23) & 1u) << 1) |  ((a1.w >> 23) & 1u);
    unsigned pb =
        (((b0.x >> 23) & 1u) << 7) | (((b0.y >> 23) & 1u) << 6) |
        (((b0.z >> 23) & 1u) << 5) | (((b0.w >> 23) & 1u) << 4) |
        (((b1.x >> 23) & 1u) << 3) | (((b1.y >> 23) & 1u) << 2) |
        (((b1.z >> 23) & 1u) << 1) |  ((b1.w >> 23) & 1u);

    unsigned sa = (pa >> 7) & 1u, ea = (pa >> 3) & 15u, ma = pa & 7u;
    unsigned sb = (pb >> 7) & 1u, eb = (pb >> 3) & 15u, mb = pb & 7u;

    bool sel = (ea >= eb);
    unsigned el = sel ? ea : eb;
    unsigned es = sel ? eb : ea;
    unsigned ml = sel ? ma : mb;
    unsigned ms = sel ? mb : ma;
    unsigned sl = sel ? sa : sb;
    unsigned ss = sel ? sb : sa;

    unsigned diff = el - es;

    unsigned extl = ((el != 0u) ? 0x400u : 0u) | (ml << 7);
    unsigned exts = (((es != 0u) ? 0x400u : 0u) | (ms << 7)) >> diff;

    unsigned mant = (sl == ss) ? ((extl + exts) & 0xFFFu)
                               : ((extl - exts) & 0xFFFu);

    unsigned top8 = mant >> 4;
    unsigned lzc = top8 ? (unsigned)(__clz((int)top8) - 24) : 7u;
    unsigned norm = (top8 << lzc) & 0xFFu;
    unsigned en = (el - lzc + 1u) & 15u;

    const unsigned ONE = 0x3F800000u;
    o0.x = sl * ONE;
    o0.y = ((en >> 3) & 1u) * ONE;
    o0.z = ((en >> 2) & 1u) * ONE;
    o0.w = ((en >> 1) & 1u) * ONE;
    o1.x = (en & 1u) * ONE;
    o1.y = ((norm >> 6) & 1u) * ONE;
    o1.z = ((norm >> 5) & 1u) * ONE;
    o1.w = ((norm >> 4) & 1u) * ONE;
}

__global__ __launch_bounds__(128) void fp8add_kernel2(
    const uint4* __restrict__ A,
    const uint4* __restrict__ B,
    uint4* __restrict__ O,
    int half)   // nrows / 2
{
    int i = blockIdx.x * blockDim.x + threadIdx.x;
    if (i >= half) return;
    int j = i + half;

    // Front-batch all 8 loads (streaming, evict-first) for maximum MLP.
    uint4 a0 = __ldcs(&A[2 * i + 0]);
    uint4 a1 = __ldcs(&A[2 * i + 1]);
    uint4 b0 = __ldcs(&B[2 * i + 0]);
    uint4 b1 = __ldcs(&B[2 * i + 1]);
    uint4 c0 = __ldcs(&A[2 * j + 0]);
    uint4 c1 = __ldcs(&A[2 * j + 1]);
    uint4 d0 = __ldcs(&B[2 * j + 0]);
    uint4 d1 = __ldcs(&B[2 * j + 1]);

    uint4 o0, o1;
    fp8add_row(a0, a1, b0, b1, o0, o1);
    __stcs(&O[2 * i + 0], o0);
    __stcs(&O[2 * i + 1], o1);

    fp8add_row(c0, c1, d0, d1, o0, o1);
    __stcs(&O[2 * j + 0], o0);
    __stcs(&O[2 * j + 1], o1);
}

__global__ __launch_bounds__(128) void fp8add_tail(
    const uint4* __restrict__ A,
    const uint4* __restrict__ B,
    uint4* __restrict__ O,
    int nrows, int start)
{
    int i = start + blockIdx.x * blockDim.x + threadIdx.x;
    if (i >= nrows) return;
    uint4 a0 = __ldcs(&A[2 * i + 0]);
    uint4 a1 = __ldcs(&A[2 * i + 1]);
    uint4 b0 = __ldcs(&B[2 * i + 0]);
    uint4 b1 = __ldcs(&B[2 * i + 1]);
    uint4 o0, o1;
    fp8add_row(a0, a1, b0, b1, o0, o1);
    __stcs(&O[2 * i + 0], o0);
    __stcs(&O[2 * i + 1], o1);
}

extern "C" void kernel_launch(void* const* d_in, const int* in_sizes, int n_in,
                              void* d_out, int out_size)
{
    const uint4* A = (const uint4*)d_in[0];
    const uint4* B = (const uint4*)d_in[1];
    uint4* O = (uint4*)d_out;

    int nrows = in_sizes[0] / 8;
    int half = nrows >> 1;
    int threads = 128;

    if (half > 0) {
        int blocks = (half + threads - 1) / threads;
        fp8add_kernel2<<<blocks, threads>>>(A, B, O, half);
    }
    if (nrows & 1) {
        // odd tail row (not hit for N=4194304, kept for generality)
        fp8add_tail<<<1, threads>>>(A, B, O, nrows, nrows - 1);
    }
}

// round 9
// speedup vs baseline: 1.1364x; 1.0047x over previous
#include <cuda_runtime.h>
#include <stdint.h>

// SpikeFP8Adder_Spatial: soft-logic E4M3 adder on {0,1}-valued float bit vectors.
// Exact 0/1 inputs => gate network collapses to integer bit logic.
// Pure HBM-bound (384 MB, 2:1 read:write => ~81% of spec is the practical ceiling).
// R8: best-known config (R2: 2 strided rows/thread, 8 front-batched streaming
// loads, fire-and-exit CTAs) with 128-thread blocks for finer CTA quantization
// (6x256=1536 -> 13x128=1664 resident threads/SM at 38 regs).

__device__ __forceinline__ void fp8add_row(
    const uint4& a0, const uint4& a1,
    const uint4& b0, const uint4& b1,
    uint4& o0, uint4& o1)
{
    // Pack MSB-first: index 0 -> bit7 ... index 7 -> bit0. 1.0f = 0x3F800000 (bit 23 set).
    unsigned pa =
        (((a0.x >> 23) & 1u) << 7) | (((a0.y >> 23) & 1u) << 6) |
        (((a0.z >> 23) & 1u) << 5) | (((a0.w >> 23) & 1u) << 4) |
        (((a1.x >> 23) & 1u) << 3) | (((a1.y >> 23) & 1u) << 2) |
        (((a1.z >> 23) & 1u) << 1) |  ((a1.w >> 23) & 1u);
    unsigned pb =
        (((b0.x >> 23) & 1u) << 7) | (((b0.y >> 23) & 1u) << 6) |
        (((b0.z >> 23) & 1u) << 5) | (((b0.w >> 23) & 1u) << 4) |
        (((b1.x >> 23) & 1u) << 3) | (((b1.y >> 23) & 1u) << 2) |
        (((b1.z >> 23) & 1u) << 1) |  ((b1.w >> 23) & 1u);

    unsigned sa = (pa >> 7) & 1u, ea = (pa >> 3) & 15u, ma = pa & 7u;
    unsigned sb = (pb >> 7) & 1u, eb = (pb >> 3) & 15u, mb = pb & 7u;

    bool sel = (ea >= eb);
    unsigned el = sel ? ea : eb;
    unsigned es = sel ? eb : ea;
    unsigned ml = sel ? ma : mb;
    unsigned ms = sel ? mb : ma;
    unsigned sl = sel ? sa : sb;
    unsigned ss = sel ? sb : sa;

    unsigned diff = el - es;

    unsigned extl = ((el != 0u) ? 0x400u : 0u) | (ml << 7);
    unsigned exts = (((es != 0u) ? 0x400u : 0u) | (ms << 7)) >> diff;

    unsigned mant = (sl == ss) ? ((extl + exts) & 0xFFFu)
                               : ((extl - exts) & 0xFFFu);

    unsigned top8 = mant >> 4;
    unsigned lzc = top8 ? (unsigned)(__clz((int)top8) - 24) : 7u;
    unsigned norm = (top8 << lzc) & 0xFFu;
    unsigned en = (el - lzc + 1u) & 15u;

    const unsigned ONE = 0x3F800000u;
    o0.x = sl * ONE;
    o0.y = ((en >> 3) & 1u) * ONE;
    o0.z = ((en >> 2) & 1u) * ONE;
    o0.w = ((en >> 1) & 1u) * ONE;
    o1.x = (en & 1u) * ONE;
    o1.y = ((norm >> 6) & 1u) * ONE;
    o1.z = ((norm >> 5) & 1u) * ONE;
    o1.w = ((norm >> 4) & 1u) * ONE;
}

__global__ __launch_bounds__(128) void fp8add_kernel2(
    const uint4* __restrict__ A,
    const uint4* __restrict__ B,
    uint4* __restrict__ O,
    int half)   // nrows / 2
{
    int i = blockIdx.x * blockDim.x + threadIdx.x;
    if (i >= half) return;
    int j = i + half;

    // Front-batch all 8 loads (streaming, evict-first) for maximum MLP.
    uint4 a0 = __ldcs(&A[2 * i + 0]);
    uint4 a1 = __ldcs(&A[2 * i + 1]);
    uint4 b0 = __ldcs(&B[2 * i + 0]);
    uint4 b1 = __ldcs(&B[2 * i + 1]);
    uint4 c0 = __ldcs(&A[2 * j + 0]);
    uint4 c1 = __ldcs(&A[2 * j + 1]);
    uint4 d0 = __ldcs(&B[2 * j + 0]);
    uint4 d1 = __ldcs(&B[2 * j + 1]);

    uint4 o0, o1;
    fp8add_row(a0, a1, b0, b1, o0, o1);
    __stcs(&O[2 * i + 0], o0);
    __stcs(&O[2 * i + 1], o1);

    fp8add_row(c0, c1, d0, d1, o0, o1);
    __stcs(&O[2 * j + 0], o0);
    __stcs(&O[2 * j + 1], o1);
}

__global__ __launch_bounds__(128) void fp8add_tail(
    const uint4* __restrict__ A,
    const uint4* __restrict__ B,
    uint4* __restrict__ O,
    int nrows, int start)
{
    int i = start + blockIdx.x * blockDim.x + threadIdx.x;
    if (i >= nrows) return;
    uint4 a0 = __ldcs(&A[2 * i + 0]);
    uint4 a1 = __ldcs(&A[2 * i + 1]);
    uint4 b0 = __ldcs(&B[2 * i + 0]);
    uint4 b1 = __ldcs(&B[2 * i + 1]);
    uint4 o0, o1;
    fp8add_row(a0, a1, b0, b1, o0, o1);
    __stcs(&O[2 * i + 0], o0);
    __stcs(&O[2 * i + 1], o1);
}

extern "C" void kernel_launch(void* const* d_in, const int* in_sizes, int n_in,
                              void* d_out, int out_size)
{
    const uint4* A = (const uint4*)d_in[0];
    const uint4* B = (const uint4*)d_in[1];
    uint4* O = (uint4*)d_out;

    int nrows = in_sizes[0] / 8;
    int half = nrows >> 1;
    int threads = 128;

    if (half > 0) {
        int blocks = (half + threads - 1) / threads;
        fp8add_kernel2<<<blocks, threads>>>(A, B, O, half);
    }
    if (nrows & 1) {
        // odd tail row (not hit for N=4194304, kept for generality)
        fp8add_tail<<<1, threads>>>(A, B, O, nrows, nrows - 1);
    }
}